// round 8
// baseline (speedup 1.0000x reference)
#include <cuda_runtime.h>
#include <cstdint>
#include <math.h>

#define N_NODES   50000
#define N_EDGES   800000
#define HDIM      96
#define NUM_IN    11
#define PE_DIM    24
#define N_LAYERS  4
#define N_GRAPHS  256

// ---------------- scratch (device globals; no allocations allowed) ----------
__device__ float g_h   [N_NODES * HDIM];
__device__ float g_A   [N_NODES * HDIM];
__device__ float g_B   [N_NODES * HDIM];
__device__ float g_aggr[N_NODES * HDIM];
__device__ float g_u   [N_NODES * HDIM];
__device__ float g_dist[N_EDGES];
__device__ int   g_send[N_EDGES];
__device__ int   g_rec [N_EDGES];
__device__ float g_pooled[N_GRAPHS * HDIM];
// transposed weights WT[n][k]: per layer: A(9216) B(9216) M2(9216) U1(18432) U2(9216)
// then E2 @ 221184, P1 @ 230400, P2 @ 239616
__device__ float g_WT[248832];

__device__ __forceinline__ float silu_f(float v) {
    return v / (1.0f + __expf(-v));
}
__device__ __forceinline__ void red_add_v4(float* p, float4 v) {
    asm volatile("red.global.add.v4.f32 [%0], {%1,%2,%3,%4};"
                 :: "l"(p), "f"(v.x), "f"(v.y), "f"(v.z), "f"(v.w) : "memory");
}
__device__ __forceinline__ uint32_t tf32c(float f) {
    uint32_t r;
    asm("cvt.rna.tf32.f32 %0, %1;" : "=r"(r) : "f"(f));
    return r;
}
// split x into hi (tf32) + lo (tf32 of residual)
__device__ __forceinline__ void tf32split(float x, uint32_t& hi, uint32_t& lo) {
    hi = tf32c(x);
    lo = tf32c(x - __uint_as_float(hi));
}
__device__ __forceinline__ void mma8(float* d, uint32_t a0, uint32_t a1,
                                     uint32_t a2, uint32_t a3,
                                     uint32_t b0, uint32_t b1) {
    asm volatile(
        "mma.sync.aligned.m16n8k8.row.col.f32.tf32.tf32.f32 "
        "{%0,%1,%2,%3}, {%4,%5,%6,%7}, {%8,%9}, {%0,%1,%2,%3};"
        : "+f"(d[0]), "+f"(d[1]), "+f"(d[2]), "+f"(d[3])
        : "r"(a0), "r"(a1), "r"(a2), "r"(a3), "r"(b0), "r"(b1));
}

// SMEM operand layout: X[row][c4][kq]  addr(floats) = row*100 + c4*24 + kq
// (c4 = k%4, kq = k/4; row stride 100 floats -> conflict-free LDS.128 frags)
#define RS 100
// float offsets in dynamic SMEM
#define AHI 0
#define BHI 12800
#define ALO 22400
#define BLO 35200
#define XTR 44800   // edge-kernel extras

// ---------------- edge preprocessing (indices + dist), dtype-robust ---------
__global__ void edge_prep(const int* __restrict__ eraw, const float* __restrict__ pos) {
    __shared__ int s_is64;
    if (threadIdx.x == 0) {
        s_is64 = ((eraw[2*N_EDGES-1] | eraw[2*N_EDGES-3] |
                   eraw[2*N_EDGES-5] | eraw[2*N_EDGES-7]) == 0) ? 1 : 0;
    }
    __syncthreads();
    int e = blockIdx.x * blockDim.x + threadIdx.x;
    if (e >= N_EDGES) return;
    int s, r;
    if (s_is64) {
        const long long* e64 = (const long long*)eraw;
        s = (int)e64[e]; r = (int)e64[N_EDGES + e];
    } else {
        s = eraw[e];     r = eraw[N_EDGES + e];
    }
    g_send[e] = s; g_rec[e] = r;
    float dx = pos[3*s+0] - pos[3*r+0];
    float dy = pos[3*s+1] - pos[3*r+1];
    float dz = pos[3*s+2] - pos[3*r+2];
    g_dist[e] = sqrtf(dx*dx + dy*dy + dz*dz);
}

// ---------------- weight transpose (all matrices, one launch) ---------------
__global__ void __launch_bounds__(1024)
transpose_all(const float* __restrict__ mw1, const float* __restrict__ mw2,
              const float* __restrict__ uw1, const float* __restrict__ uw2,
              const float* __restrict__ ew2, const float* __restrict__ pw1,
              const float* __restrict__ pw2)
{
    __shared__ float t[32][33];
    int bid = blockIdx.x;
    const float* src; float* dst; int K; int tile;
    if (bid < 216) {
        int l = bid / 54, sub = bid % 54;
        float* WTl = g_WT + l * 55296;
        if (sub < 9)       { src = mw1 + (size_t)l*193*96;        dst = WTl;         K = 96;  tile = sub; }
        else if (sub < 18) { src = mw1 + (size_t)l*193*96 + 9216; dst = WTl + 9216;  K = 96;  tile = sub - 9; }
        else if (sub < 27) { src = mw2 + (size_t)l*9216;          dst = WTl + 18432; K = 96;  tile = sub - 18; }
        else if (sub < 45) { src = uw1 + (size_t)l*18432;         dst = WTl + 27648; K = 192; tile = sub - 27; }
        else               { src = uw2 + (size_t)l*9216;          dst = WTl + 46080; K = 96;  tile = sub - 45; }
    } else if (bid < 225) { src = ew2; dst = g_WT + 221184; K = 96; tile = bid - 216; }
    else if (bid < 234)   { src = pw1; dst = g_WT + 230400; K = 96; tile = bid - 225; }
    else                  { src = pw2; dst = g_WT + 239616; K = 96; tile = bid - 234; }
    int bx = tile % 3, by = tile / 3;
    int tx = threadIdx.x & 31, ty = threadIdx.x >> 5;
    t[ty][tx] = src[(by*32 + ty) * 96 + bx*32 + tx];
    __syncthreads();
    dst[(bx*32 + ty) * K + by*32 + tx] = t[tx][ty];
}

// ---- shared 3xTF32 mainloop (A/B hi+lo already in SMEM) --------------------
__device__ __forceinline__ void mma3_loop(const uint32_t* ap, const uint32_t* bp,
                                          float acc[4][3][4])
{
    #pragma unroll
    for (int i = 0; i < 6; i++) {
        uint4 al[4], ah[4], all[4], ahl[4];
        #pragma unroll
        for (int mf = 0; mf < 4; mf++) {
            al [mf] = *(const uint4*)(ap + mf * 1600 + 4 * i);
            ah [mf] = *(const uint4*)(ap + mf * 1600 + 800 + 4 * i);
            all[mf] = *(const uint4*)(ap + ALO - AHI + mf * 1600 + 4 * i);
            ahl[mf] = *(const uint4*)(ap + ALO - AHI + mf * 1600 + 800 + 4 * i);
        }
        #pragma unroll
        for (int nf = 0; nf < 3; nf++) {
            uint4 bh = *(const uint4*)(bp + nf * 800 + 4 * i);
            uint4 bl = *(const uint4*)(bp + BLO - BHI + nf * 800 + 4 * i);
            #pragma unroll
            for (int mf = 0; mf < 4; mf++) {
                // k16 chunk 1: hi*hi + hi*lo + lo*hi
                mma8(acc[mf][nf], al[mf].x, ah[mf].x, al[mf].y, ah[mf].y, bh.x, bh.y);
                mma8(acc[mf][nf], al[mf].x, ah[mf].x, al[mf].y, ah[mf].y, bl.x, bl.y);
                mma8(acc[mf][nf], all[mf].x, ahl[mf].x, all[mf].y, ahl[mf].y, bh.x, bh.y);
                // k16 chunk 2
                mma8(acc[mf][nf], al[mf].z, ah[mf].z, al[mf].w, ah[mf].w, bh.z, bh.w);
                mma8(acc[mf][nf], al[mf].z, ah[mf].z, al[mf].w, ah[mf].w, bl.z, bl.w);
                mma8(acc[mf][nf], all[mf].z, ahl[mf].z, all[mf].w, ahl[mf].w, bh.z, bh.w);
            }
        }
    }
}

// ---------------- mma node MLP: out = act([in1|in2] @ W + b)[+res] ----------
// 256 thr = 8 warps (2 m x 4 n), CTA tile 128 rows x 96 cols, K in 96-chunks
__global__ void __launch_bounds__(256)
mma_node(const float* __restrict__ in1, const float* __restrict__ in2,
         const float* __restrict__ WT, int Ktot,
         const float* __restrict__ bias, const float* __restrict__ res,
         float* __restrict__ out, int nrows, int do_silu)
{
    extern __shared__ float sm[];
    uint32_t* As  = (uint32_t*)(sm + AHI);
    uint32_t* Bs  = (uint32_t*)(sm + BHI);
    uint32_t* Asl = (uint32_t*)(sm + ALO);
    uint32_t* Bsl = (uint32_t*)(sm + BLO);
    float*    Cs  = sm;

    const int tid = threadIdx.x;
    const int w   = tid >> 5, lane = tid & 31;
    const int wm  = w & 1, wn = w >> 1;
    const int tr  = lane >> 2, tc = lane & 3;
    const int base = blockIdx.x * 128;

    float acc[4][3][4];
    #pragma unroll
    for (int mf = 0; mf < 4; mf++)
        #pragma unroll
        for (int nf = 0; nf < 3; nf++)
            #pragma unroll
            for (int c = 0; c < 4; c++) acc[mf][nf][c] = 0.0f;

    const int nchunk = Ktot / 96;
    for (int ch = 0; ch < nchunk; ch++) {
        const float* src = (ch == 0) ? in1 : in2;
        #pragma unroll
        for (int it = 0; it < 12; it++) {
            int idx = it * 256 + tid;
            int row = idx / 24, k4 = idx - row * 24;
            int grow = base + row;
            float4 v = make_float4(0.f, 0.f, 0.f, 0.f);
            if (grow < nrows) v = *(const float4*)&src[(size_t)grow * 96 + k4 * 4];
            uint32_t *d = As + row * RS + k4, *dl = Asl + row * RS + k4;
            tf32split(v.x, d[0],  dl[0]);
            tf32split(v.y, d[24], dl[24]);
            tf32split(v.z, d[48], dl[48]);
            tf32split(v.w, d[72], dl[72]);
        }
        #pragma unroll
        for (int it = 0; it < 9; it++) {
            int idx = it * 256 + tid;
            int n = idx / 24, k4 = idx - n * 24;
            float4 v = *(const float4*)&WT[(size_t)n * Ktot + ch * 96 + k4 * 4];
            uint32_t *d = Bs + n * RS + k4, *dl = Bsl + n * RS + k4;
            tf32split(v.x, d[0],  dl[0]);
            tf32split(v.y, d[24], dl[24]);
            tf32split(v.z, d[48], dl[48]);
            tf32split(v.w, d[72], dl[72]);
        }
        __syncthreads();

        const uint32_t* ap = As + (wm * 64 + tr) * RS + tc * 24;
        const uint32_t* bp = Bs + (wn * 24 + tr) * RS + tc * 24;
        mma3_loop(ap, bp, acc);
        __syncthreads();
    }

    // stage C into SMEM (row stride RS)
    #pragma unroll
    for (int mf = 0; mf < 4; mf++) {
        int row = wm * 64 + mf * 16 + tr;
        #pragma unroll
        for (int nf = 0; nf < 3; nf++) {
            int col = wn * 24 + nf * 8 + 2 * tc;
            Cs[row * RS + col]       = acc[mf][nf][0];
            Cs[row * RS + col + 1]   = acc[mf][nf][1];
            Cs[(row+8) * RS + col]   = acc[mf][nf][2];
            Cs[(row+8) * RS + col+1] = acc[mf][nf][3];
        }
    }
    __syncthreads();

    #pragma unroll
    for (int it = 0; it < 12; it++) {
        int idx = it * 256 + tid;
        int row = idx / 24, j4 = idx - row * 24;
        int grow = base + row;
        if (grow >= nrows) continue;
        float4 v = *(const float4*)&Cs[row * RS + j4 * 4];
        if (bias) {
            float4 b = *(const float4*)&bias[j4 * 4];
            v.x += b.x; v.y += b.y; v.z += b.z; v.w += b.w;
        }
        if (do_silu) {
            v.x = silu_f(v.x); v.y = silu_f(v.y);
            v.z = silu_f(v.z); v.w = silu_f(v.w);
        }
        if (res) {
            float4 rv = *(const float4*)&res[(size_t)grow * 96 + j4 * 4];
            v.x += rv.x; v.y += rv.y; v.z += rv.z; v.w += rv.w;
        }
        *(float4*)&out[(size_t)grow * 96 + j4 * 4] = v;
    }
}

// ---------------- mma fused edge message + aggregation ----------------------
// t = silu(A[send]+B[rec]+d*wl+b1); m = silu(t@W2+b2); aggr[rec] += m
__global__ void __launch_bounds__(256)
mma_edge(const float* __restrict__ WT2, const float* __restrict__ wl,
         const float* __restrict__ b1, const float* __restrict__ b2)
{
    extern __shared__ float sm[];
    uint32_t* As  = (uint32_t*)(sm + AHI);
    uint32_t* Bs  = (uint32_t*)(sm + BHI);
    uint32_t* Asl = (uint32_t*)(sm + ALO);
    uint32_t* Bsl = (uint32_t*)(sm + BLO);
    float*    Cs  = sm;
    float* b1s = sm + XTR;
    float* b2s = b1s + 96;
    float* wls = b2s + 96;
    float* de  = wls + 96;
    int*   se  = (int*)(de + 128);
    int*   re  = se + 128;

    const int tid = threadIdx.x;
    const int w   = tid >> 5, lane = tid & 31;
    const int wm  = w & 1, wn = w >> 1;
    const int tr  = lane >> 2, tc = lane & 3;
    const int base = blockIdx.x * 128;

    if (tid < 96) { b1s[tid] = b1[tid]; b2s[tid] = b2[tid]; wls[tid] = wl[tid]; }
    else if (tid >= 128) {
        int j = tid - 128; int e = base + j;
        se[j] = g_send[e]; re[j] = g_rec[e]; de[j] = g_dist[e];
    }
    #pragma unroll
    for (int it = 0; it < 9; it++) {
        int idx = it * 256 + tid;
        int n = idx / 24, k4 = idx - n * 24;
        float4 v = *(const float4*)&WT2[(size_t)n * 96 + k4 * 4];
        uint32_t *d = Bs + n * RS + k4, *dl = Bsl + n * RS + k4;
        tf32split(v.x, d[0],  dl[0]);
        tf32split(v.y, d[24], dl[24]);
        tf32split(v.z, d[48], dl[48]);
        tf32split(v.w, d[72], dl[72]);
    }
    __syncthreads();

    #pragma unroll
    for (int it = 0; it < 12; it++) {
        int idx = it * 256 + tid;
        int e = idx / 24, k4 = idx - e * 24;
        int kf = k4 * 4;
        int s = se[e], r = re[e];
        float dd = de[e];
        float4 a  = *(const float4*)&g_A[(size_t)s * 96 + kf];
        float4 b  = *(const float4*)&g_B[(size_t)r * 96 + kf];
        float4 w4 = *(const float4*)&wls[kf];
        float4 c4 = *(const float4*)&b1s[kf];
        uint32_t *d = As + e * RS + k4, *dl = Asl + e * RS + k4;
        tf32split(silu_f(a.x + b.x + dd * w4.x + c4.x), d[0],  dl[0]);
        tf32split(silu_f(a.y + b.y + dd * w4.y + c4.y), d[24], dl[24]);
        tf32split(silu_f(a.z + b.z + dd * w4.z + c4.z), d[48], dl[48]);
        tf32split(silu_f(a.w + b.w + dd * w4.w + c4.w), d[72], dl[72]);
    }
    __syncthreads();

    float acc[4][3][4];
    #pragma unroll
    for (int mf = 0; mf < 4; mf++)
        #pragma unroll
        for (int nf = 0; nf < 3; nf++)
            #pragma unroll
            for (int c = 0; c < 4; c++) acc[mf][nf][c] = 0.0f;

    const uint32_t* ap = As + (wm * 64 + tr) * RS + tc * 24;
    const uint32_t* bp = Bs + (wn * 24 + tr) * RS + tc * 24;
    mma3_loop(ap, bp, acc);
    __syncthreads();

    #pragma unroll
    for (int mf = 0; mf < 4; mf++) {
        int row = wm * 64 + mf * 16 + tr;
        #pragma unroll
        for (int nf = 0; nf < 3; nf++) {
            int col = wn * 24 + nf * 8 + 2 * tc;
            Cs[row * RS + col]       = acc[mf][nf][0];
            Cs[row * RS + col + 1]   = acc[mf][nf][1];
            Cs[(row+8) * RS + col]   = acc[mf][nf][2];
            Cs[(row+8) * RS + col+1] = acc[mf][nf][3];
        }
    }
    __syncthreads();

    #pragma unroll
    for (int it = 0; it < 12; it++) {
        int idx = it * 256 + tid;
        int row = idx / 24, j4 = idx - row * 24;
        float4 v = *(const float4*)&Cs[row * RS + j4 * 4];
        float4 b = *(const float4*)&b2s[j4 * 4];
        float4 m;
        m.x = silu_f(v.x + b.x); m.y = silu_f(v.y + b.y);
        m.z = silu_f(v.z + b.z); m.w = silu_f(v.w + b.w);
        red_add_v4(&g_aggr[(size_t)re[row] * 96 + j4 * 4], m);
    }
}

// ---------------- scalar node MLP (embed layer 1 only, K=11+24) -------------
__global__ void __launch_bounds__(384, 2)
node_mlp(const float* __restrict__ in1, int K1, const float* __restrict__ W1,
         const float* __restrict__ in2, int K2, const float* __restrict__ W2,
         const float* __restrict__ bias, float* __restrict__ out,
         int nrows, int do_silu)
{
    extern __shared__ float smf[];
    const int K1p = (K1 + 3) & ~3;
    const int K2p = (K2 + 3) & ~3;
    float* Ws1 = smf;
    float* Ws2 = smf + K1p * 96;
    float* sT  = Ws2 + K2p * 96;

    const int tid  = threadIdx.y * 24 + threadIdx.x;
    const int base = blockIdx.x * 64;
    const int f0   = threadIdx.x * 4;
    const int r0   = threadIdx.y * 4;

    for (int idx = tid; idx < K1p * 96; idx += 384) {
        int k = idx / 96;
        Ws1[idx] = (k < K1) ? W1[idx] : 0.0f;
    }
    if (in2) {
        for (int idx = tid; idx < K2p * 96; idx += 384) {
            int k = idx / 96;
            Ws2[idx] = (k < K2) ? W2[idx] : 0.0f;
        }
    }

    float acc[4][4];
    #pragma unroll
    for (int i = 0; i < 4; i++)
        #pragma unroll
        for (int c = 0; c < 4; c++) acc[i][c] = 0.0f;

    for (int idx = tid; idx < 64 * K1p; idx += 384) {
        int k = idx / 64, e = idx - (k * 64);
        int row = base + e;
        sT[k*64 + e] = (k < K1 && row < nrows) ? in1[(size_t)row * K1 + k] : 0.0f;
    }
    __syncthreads();
    for (int k = 0; k < K1p; k++) {
        float4 w = *(const float4*)&Ws1[k*96 + f0];
        #pragma unroll
        for (int i = 0; i < 4; i++) {
            float tv = sT[k*64 + r0 + i];
            acc[i][0] += tv * w.x; acc[i][1] += tv * w.y;
            acc[i][2] += tv * w.z; acc[i][3] += tv * w.w;
        }
    }
    if (in2) {
        __syncthreads();
        for (int idx = tid; idx < 64 * K2p; idx += 384) {
            int k = idx / 64, e = idx - (k * 64);
            int row = base + e;
            sT[k*64 + e] = (k < K2 && row < nrows) ? in2[(size_t)row * K2 + k] : 0.0f;
        }
        __syncthreads();
        for (int k = 0; k < K2p; k++) {
            float4 w = *(const float4*)&Ws2[k*96 + f0];
            #pragma unroll
            for (int i = 0; i < 4; i++) {
                float tv = sT[k*64 + r0 + i];
                acc[i][0] += tv * w.x; acc[i][1] += tv * w.y;
                acc[i][2] += tv * w.z; acc[i][3] += tv * w.w;
            }
        }
    }
    #pragma unroll
    for (int i = 0; i < 4; i++) {
        int row = base + r0 + i;
        if (row >= nrows) continue;
        float4 v;
        v.x = acc[i][0] + bias[f0+0];
        v.y = acc[i][1] + bias[f0+1];
        v.z = acc[i][2] + bias[f0+2];
        v.w = acc[i][3] + bias[f0+3];
        if (do_silu) {
            v.x = silu_f(v.x); v.y = silu_f(v.y);
            v.z = silu_f(v.z); v.w = silu_f(v.w);
        }
        *(float4*)&out[(size_t)row*96 + f0] = v;
    }
}

// ---------------- zero / pooling / readout ----------------------------------
__global__ void zero_aggr_kernel() {
    int i = blockIdx.x * 1024 + threadIdx.x;
    if (i < N_NODES * HDIM) g_aggr[i] = 0.0f;
}
__global__ void zero_pooled_kernel() {
    int i = blockIdx.x * 256 + threadIdx.x;
    if (i < N_GRAPHS * HDIM) g_pooled[i] = 0.0f;
}
__global__ void pool_kernel(const float* __restrict__ h2, const int* __restrict__ braw) {
    __shared__ int s_is64;
    if (threadIdx.x == 0) {
        s_is64 = ((braw[N_NODES-1] | braw[N_NODES-3] |
                   braw[N_NODES-5] | braw[N_NODES-7]) == 0) ? 1 : 0;
    }
    __syncthreads();
    int idx = blockIdx.x * blockDim.x + threadIdx.x;
    if (idx >= N_NODES * 24) return;
    int n = idx / 24, j = idx - n * 24;
    int g = s_is64 ? (int)((const long long*)braw)[n] : braw[n];
    float4 v = *(const float4*)&h2[(size_t)n*96 + j*4];
    red_add_v4(&g_pooled[g*96 + j*4], v);
}
__global__ void readout_kernel(const float* __restrict__ w1, const float* __restrict__ b1,
                               const float* __restrict__ w2, const float* __restrict__ b2,
                               float* __restrict__ out)
{
    __shared__ float p_s[96];
    __shared__ float t_s[96];
    int g = blockIdx.x, f = threadIdx.x;
    p_s[f] = g_pooled[g*96 + f];
    __syncthreads();
    float a = b1[f];
    #pragma unroll 8
    for (int k = 0; k < 96; k++) a += p_s[k] * w1[k*96 + f];
    t_s[f] = silu_f(a) * w2[f];
    __syncthreads();
    if (f < 32) {
        float sum = t_s[f] + t_s[f+32] + t_s[f+64];
        #pragma unroll
        for (int o = 16; o > 0; o >>= 1) sum += __shfl_down_sync(0xffffffffu, sum, o);
        if (f == 0) out[g] = sum + b2[0];
    }
}

// ---------------- host launcher ----------------------------------------------
extern "C" void kernel_launch(void* const* d_in, const int* in_sizes, int n_in,
                              void* d_out, int out_size)
{
    const float* x    = (const float*)d_in[0];
    const float* pos  = (const float*)d_in[1];
    const float* pe   = (const float*)d_in[2];
    const int*   eraw = (const int*)d_in[3];
    const int*   braw = (const int*)d_in[4];
    const float* ew1  = (const float*)d_in[5];
    const float* eb1  = (const float*)d_in[6];
    const float* ew2  = (const float*)d_in[7];
    const float* eb2  = (const float*)d_in[8];
    const float* mw1  = (const float*)d_in[9];
    const float* mb1  = (const float*)d_in[10];
    const float* mw2  = (const float*)d_in[11];
    const float* mb2  = (const float*)d_in[12];
    const float* uw1  = (const float*)d_in[13];
    const float* ub1  = (const float*)d_in[14];
    const float* uw2  = (const float*)d_in[15];
    const float* ub2  = (const float*)d_in[16];
    const float* pw1  = (const float*)d_in[17];
    const float* pb1  = (const float*)d_in[18];
    const float* pw2  = (const float*)d_in[19];
    const float* pb2  = (const float*)d_in[20];
    const float* rw1  = (const float*)d_in[21];
    const float* rb1  = (const float*)d_in[22];
    const float* rw2  = (const float*)d_in[23];
    const float* rb2  = (const float*)d_in[24];
    float* out = (float*)d_out;

    float *h_, *A_, *B_, *aggr_, *u_, *WT_;
    cudaGetSymbolAddress((void**)&h_,    g_h);
    cudaGetSymbolAddress((void**)&A_,    g_A);
    cudaGetSymbolAddress((void**)&B_,    g_B);
    cudaGetSymbolAddress((void**)&aggr_, g_aggr);
    cudaGetSymbolAddress((void**)&u_,    g_u);
    cudaGetSymbolAddress((void**)&WT_,   g_WT);

    cudaFuncSetAttribute((const void*)node_mlp,
                         cudaFuncAttributeMaxDynamicSharedMemorySize, 32768);
    cudaFuncSetAttribute((const void*)mma_node,
                         cudaFuncAttributeMaxDynamicSharedMemorySize, 180224);
    cudaFuncSetAttribute((const void*)mma_edge,
                         cudaFuncAttributeMaxDynamicSharedMemorySize, 184320);

    // smem: hi/lo A (2*12800) + hi/lo B (2*9600) = 44800 floats = 179200 B
    const size_t smN = 179200;
    const size_t smE = 179200 + (96*3 + 128*3) * 4;   // 181888
    const int    nblk = (N_NODES + 127) / 128;        // 391

    edge_prep<<<(N_EDGES + 255) / 256, 256>>>(eraw, pos);
    transpose_all<<<243, 1024>>>(mw1, mw2, uw1, uw2, ew2, pw1, pw2);

    // embed layer 1 (scalar, K=11+24): u = silu([x,pe]@W1 + b1)
    {
        int K1p = 12, K2p = 24;
        size_t smem = (size_t)(K1p + K2p) * 96 * 4 + (size_t)64 * 24 * 4;
        dim3 tb(24, 16);
        node_mlp<<<(N_NODES + 63) / 64, tb, smem>>>(
            x, NUM_IN, ew1, pe, PE_DIM, ew1 + NUM_IN * 96, eb1, u_, N_NODES, 1);
    }
    // embed layer 2: h = u @ W2 + b2
    mma_node<<<nblk, 256, smN>>>(u_, nullptr, WT_ + 221184, 96, eb2, nullptr, h_, N_NODES, 0);

    for (int l = 0; l < N_LAYERS; l++) {
        float* WTl = WT_ + (size_t)l * 55296;
        const float* mb1l = mb1 + l * 96;
        const float* mb2l = mb2 + l * 96;
        const float* ub1l = ub1 + l * 96;
        const float* ub2l = ub2 + l * 96;
        const float* wll  = mw1 + (size_t)l * 193 * 96 + 192 * 96;  // dist row

        mma_node<<<nblk, 256, smN>>>(h_, nullptr, WTl,        96, nullptr, nullptr, A_, N_NODES, 0);
        mma_node<<<nblk, 256, smN>>>(h_, nullptr, WTl + 9216, 96, nullptr, nullptr, B_, N_NODES, 0);

        zero_aggr_kernel<<<(N_NODES * HDIM + 1023) / 1024, 1024>>>();
        mma_edge<<<N_EDGES / 128, 256, smE>>>(WTl + 18432, wll, mb1l, mb2l);

        mma_node<<<nblk, 256, smN>>>(h_, aggr_, WTl + 27648, 192, ub1l, nullptr, u_, N_NODES, 1);
        mma_node<<<nblk, 256, smN>>>(u_, nullptr, WTl + 46080, 96, ub2l, h_, h_, N_NODES, 0);
    }

    // pre-MLP -> h2 (stored in g_A)
    mma_node<<<nblk, 256, smN>>>(h_, nullptr, WT_ + 230400, 96, pb1, nullptr, u_, N_NODES, 1);
    mma_node<<<nblk, 256, smN>>>(u_, nullptr, WT_ + 239616, 96, pb2, nullptr, A_, N_NODES, 0);

    zero_pooled_kernel<<<(N_GRAPHS * HDIM + 255) / 256, 256>>>();
    pool_kernel<<<(N_NODES * 24 + 255) / 256, 256>>>(A_, braw);
    readout_kernel<<<N_GRAPHS, 96>>>(rw1, rb1, rw2, rb2, out);
}

// round 9
// speedup vs baseline: 1.2664x; 1.2664x over previous
#include <cuda_runtime.h>
#include <cstdint>
#include <math.h>

#define N_NODES   50000
#define N_EDGES   800000
#define HDIM      96
#define NUM_IN    11
#define PE_DIM    24
#define N_LAYERS  4
#define N_GRAPHS  256

// ---------------- scratch (device globals; no allocations allowed) ----------
__device__ float g_h   [N_NODES * HDIM];
__device__ float g_A   [N_NODES * HDIM];
__device__ float g_B   [N_NODES * HDIM];
__device__ float g_aggr[N_NODES * HDIM];
__device__ float g_u   [N_NODES * HDIM];
__device__ float g_dist[N_EDGES];
__device__ int   g_send[N_EDGES];
__device__ int   g_rec [N_EDGES];
__device__ float g_pooled[N_GRAPHS * HDIM];
// transposed weights WT[n][k]: per layer: A(9216) B(9216) M2(9216) U1(18432) U2(9216)
// then E2 @ 221184, P1 @ 230400, P2 @ 239616. After split_weights: g_WT = hi, g_WTlo = lo
__device__ float g_WT  [248832];
__device__ float g_WTlo[248832];

__device__ __forceinline__ float silu_f(float v) {
    return v / (1.0f + __expf(-v));
}
__device__ __forceinline__ void red_add_v4(float* p, float4 v) {
    asm volatile("red.global.add.v4.f32 [%0], {%1,%2,%3,%4};"
                 :: "l"(p), "f"(v.x), "f"(v.y), "f"(v.z), "f"(v.w) : "memory");
}
__device__ __forceinline__ uint32_t tf32c(float f) {
    uint32_t r;
    asm("cvt.rna.tf32.f32 %0, %1;" : "=r"(r) : "f"(f));
    return r;
}
__device__ __forceinline__ void tf32split(float x, uint32_t& hi, uint32_t& lo) {
    hi = tf32c(x);
    lo = tf32c(x - __uint_as_float(hi));
}
__device__ __forceinline__ void mma8(float* d, uint32_t a0, uint32_t a1,
                                     uint32_t a2, uint32_t a3,
                                     uint32_t b0, uint32_t b1) {
    asm volatile(
        "mma.sync.aligned.m16n8k8.row.col.f32.tf32.tf32.f32 "
        "{%0,%1,%2,%3}, {%4,%5,%6,%7}, {%8,%9}, {%0,%1,%2,%3};"
        : "+f"(d[0]), "+f"(d[1]), "+f"(d[2]), "+f"(d[3])
        : "r"(a0), "r"(a1), "r"(a2), "r"(a3), "r"(b0), "r"(b1));
}

// SMEM operand layout: X[row][c4][kq]  addr(floats) = row*100 + c4*24 + kq
// (c4 = k%4, kq = k/4; row stride 100 floats -> conflict-free LDS.128 frags)
#define RS 100
// float offsets in dynamic SMEM
#define AHI 0
#define BHI 12800
#define ALO 22400
#define BLO 35200
#define XTR 44800   // edge-kernel extras

// ---------------- edge preprocessing (indices + dist), dtype-robust ---------
__global__ void edge_prep(const int* __restrict__ eraw, const float* __restrict__ pos) {
    __shared__ int s_is64;
    if (threadIdx.x == 0) {
        s_is64 = ((eraw[2*N_EDGES-1] | eraw[2*N_EDGES-3] |
                   eraw[2*N_EDGES-5] | eraw[2*N_EDGES-7]) == 0) ? 1 : 0;
    }
    __syncthreads();
    int e = blockIdx.x * blockDim.x + threadIdx.x;
    if (e >= N_EDGES) return;
    int s, r;
    if (s_is64) {
        const long long* e64 = (const long long*)eraw;
        s = (int)e64[e]; r = (int)e64[N_EDGES + e];
    } else {
        s = eraw[e];     r = eraw[N_EDGES + e];
    }
    g_send[e] = s; g_rec[e] = r;
    float dx = pos[3*s+0] - pos[3*r+0];
    float dy = pos[3*s+1] - pos[3*r+1];
    float dz = pos[3*s+2] - pos[3*r+2];
    g_dist[e] = sqrtf(dx*dx + dy*dy + dz*dz);
}

// ---------------- weight transpose (all matrices, one launch) ---------------
__global__ void __launch_bounds__(1024)
transpose_all(const float* __restrict__ mw1, const float* __restrict__ mw2,
              const float* __restrict__ uw1, const float* __restrict__ uw2,
              const float* __restrict__ ew2, const float* __restrict__ pw1,
              const float* __restrict__ pw2)
{
    __shared__ float t[32][33];
    int bid = blockIdx.x;
    const float* src; float* dst; int K; int tile;
    if (bid < 216) {
        int l = bid / 54, sub = bid % 54;
        float* WTl = g_WT + l * 55296;
        if (sub < 9)       { src = mw1 + (size_t)l*193*96;        dst = WTl;         K = 96;  tile = sub; }
        else if (sub < 18) { src = mw1 + (size_t)l*193*96 + 9216; dst = WTl + 9216;  K = 96;  tile = sub - 9; }
        else if (sub < 27) { src = mw2 + (size_t)l*9216;          dst = WTl + 18432; K = 96;  tile = sub - 18; }
        else if (sub < 45) { src = uw1 + (size_t)l*18432;         dst = WTl + 27648; K = 192; tile = sub - 27; }
        else               { src = uw2 + (size_t)l*9216;          dst = WTl + 46080; K = 96;  tile = sub - 45; }
    } else if (bid < 225) { src = ew2; dst = g_WT + 221184; K = 96; tile = bid - 216; }
    else if (bid < 234)   { src = pw1; dst = g_WT + 230400; K = 96; tile = bid - 225; }
    else                  { src = pw2; dst = g_WT + 239616; K = 96; tile = bid - 234; }
    int bx = tile % 3, by = tile / 3;
    int tx = threadIdx.x & 31, ty = threadIdx.x >> 5;
    t[ty][tx] = src[(by*32 + ty) * 96 + bx*32 + tx];
    __syncthreads();
    dst[(bx*32 + ty) * K + by*32 + tx] = t[tx][ty];
}

// split g_WT into hi (in place) + lo (g_WTlo), tf32 bit patterns as floats
__global__ void __launch_bounds__(1024)
split_weights() {
    int i = blockIdx.x * 1024 + threadIdx.x;
    if (i >= 248832) return;
    float x = g_WT[i];
    uint32_t hi, lo;
    tf32split(x, hi, lo);
    g_WT[i]   = __uint_as_float(hi);
    g_WTlo[i] = __uint_as_float(lo);
}

// ---- shared 3xTF32 mainloop: 16 warps, warp tile 32 rows x 24 cols ----------
__device__ __forceinline__ void mma3_loop(const uint32_t* ap, const uint32_t* bp,
                                          float acc[2][3][4])
{
    #pragma unroll
    for (int i = 0; i < 6; i++) {
        uint4 al[2], ah[2], all[2], ahl[2];
        #pragma unroll
        for (int mf = 0; mf < 2; mf++) {
            al [mf] = *(const uint4*)(ap + mf * 1600 + 4 * i);
            ah [mf] = *(const uint4*)(ap + mf * 1600 + 800 + 4 * i);
            all[mf] = *(const uint4*)(ap + ALO - AHI + mf * 1600 + 4 * i);
            ahl[mf] = *(const uint4*)(ap + ALO - AHI + mf * 1600 + 800 + 4 * i);
        }
        #pragma unroll
        for (int nf = 0; nf < 3; nf++) {
            uint4 bh = *(const uint4*)(bp + nf * 800 + 4 * i);
            uint4 bl = *(const uint4*)(bp + BLO - BHI + nf * 800 + 4 * i);
            #pragma unroll
            for (int mf = 0; mf < 2; mf++) {
                // k8 chunk 1: hi*hi + hi*lo + lo*hi
                mma8(acc[mf][nf], al[mf].x, ah[mf].x, al[mf].y, ah[mf].y, bh.x, bh.y);
                mma8(acc[mf][nf], al[mf].x, ah[mf].x, al[mf].y, ah[mf].y, bl.x, bl.y);
                mma8(acc[mf][nf], all[mf].x, ahl[mf].x, all[mf].y, ahl[mf].y, bh.x, bh.y);
                // k8 chunk 2
                mma8(acc[mf][nf], al[mf].z, ah[mf].z, al[mf].w, ah[mf].w, bh.z, bh.w);
                mma8(acc[mf][nf], al[mf].z, ah[mf].z, al[mf].w, ah[mf].w, bl.z, bl.w);
                mma8(acc[mf][nf], all[mf].z, ahl[mf].z, all[mf].w, ahl[mf].w, bh.z, bh.w);
            }
        }
    }
}

// ---------------- mma node MLP: out = act([in1|in2] @ W + b)[+res] ----------
// 512 thr = 16 warps (4 m x 4 n), CTA tile 128 rows x 96 cols, K in 96-chunks
__global__ void __launch_bounds__(512, 1)
mma_node(const float* __restrict__ in1, const float* __restrict__ in2,
         const float* __restrict__ WT, const float* __restrict__ WTlo, int Ktot,
         const float* __restrict__ bias, const float* __restrict__ res,
         float* __restrict__ out, int nrows, int do_silu)
{
    extern __shared__ float sm[];
    uint32_t* As  = (uint32_t*)(sm + AHI);
    uint32_t* Bs  = (uint32_t*)(sm + BHI);
    uint32_t* Asl = (uint32_t*)(sm + ALO);
    uint32_t* Bsl = (uint32_t*)(sm + BLO);
    float*    Cs  = sm;

    const int tid = threadIdx.x;
    const int w   = tid >> 5, lane = tid & 31;
    const int wm  = w & 3, wn = w >> 2;        // 4 x 4 warp grid
    const int tr  = lane >> 2, tc = lane & 3;
    const int base = blockIdx.x * 128;

    float acc[2][3][4];
    #pragma unroll
    for (int mf = 0; mf < 2; mf++)
        #pragma unroll
        for (int nf = 0; nf < 3; nf++)
            #pragma unroll
            for (int c = 0; c < 4; c++) acc[mf][nf][c] = 0.0f;

    const int nchunk = Ktot / 96;
    for (int ch = 0; ch < nchunk; ch++) {
        const float* src = (ch == 0) ? in1 : in2;
        #pragma unroll
        for (int it = 0; it < 6; it++) {       // 128*24 / 512
            int idx = it * 512 + tid;
            int row = idx / 24, k4 = idx - row * 24;
            int grow = base + row;
            float4 v = make_float4(0.f, 0.f, 0.f, 0.f);
            if (grow < nrows) v = *(const float4*)&src[(size_t)grow * 96 + k4 * 4];
            uint32_t *d = As + row * RS + k4, *dl = Asl + row * RS + k4;
            tf32split(v.x, d[0],  dl[0]);
            tf32split(v.y, d[24], dl[24]);
            tf32split(v.z, d[48], dl[48]);
            tf32split(v.w, d[72], dl[72]);
        }
        #pragma unroll
        for (int it = 0; it < 5; it++) {       // ceil(96*24 / 512)
            int idx = it * 512 + tid;
            if (idx < 96 * 24) {
                int n = idx / 24, k4 = idx - n * 24;
                float4 vh = *(const float4*)&WT  [(size_t)n * Ktot + ch * 96 + k4 * 4];
                float4 vl = *(const float4*)&WTlo[(size_t)n * Ktot + ch * 96 + k4 * 4];
                uint32_t *d = Bs + n * RS + k4, *dl = Bsl + n * RS + k4;
                d[0]  = __float_as_uint(vh.x); dl[0]  = __float_as_uint(vl.x);
                d[24] = __float_as_uint(vh.y); dl[24] = __float_as_uint(vl.y);
                d[48] = __float_as_uint(vh.z); dl[48] = __float_as_uint(vl.z);
                d[72] = __float_as_uint(vh.w); dl[72] = __float_as_uint(vl.w);
            }
        }
        __syncthreads();

        const uint32_t* ap = As + (wm * 32 + tr) * RS + tc * 24;
        const uint32_t* bp = Bs + (wn * 24 + tr) * RS + tc * 24;
        mma3_loop(ap, bp, acc);
        __syncthreads();
    }

    // stage C into SMEM (row stride RS)
    #pragma unroll
    for (int mf = 0; mf < 2; mf++) {
        int row = wm * 32 + mf * 16 + tr;
        #pragma unroll
        for (int nf = 0; nf < 3; nf++) {
            int col = wn * 24 + nf * 8 + 2 * tc;
            Cs[row * RS + col]       = acc[mf][nf][0];
            Cs[row * RS + col + 1]   = acc[mf][nf][1];
            Cs[(row+8) * RS + col]   = acc[mf][nf][2];
            Cs[(row+8) * RS + col+1] = acc[mf][nf][3];
        }
    }
    __syncthreads();

    #pragma unroll
    for (int it = 0; it < 6; it++) {
        int idx = it * 512 + tid;
        int row = idx / 24, j4 = idx - row * 24;
        int grow = base + row;
        if (grow >= nrows) continue;
        float4 v = *(const float4*)&Cs[row * RS + j4 * 4];
        if (bias) {
            float4 b = *(const float4*)&bias[j4 * 4];
            v.x += b.x; v.y += b.y; v.z += b.z; v.w += b.w;
        }
        if (do_silu) {
            v.x = silu_f(v.x); v.y = silu_f(v.y);
            v.z = silu_f(v.z); v.w = silu_f(v.w);
        }
        if (res) {
            float4 rv = *(const float4*)&res[(size_t)grow * 96 + j4 * 4];
            v.x += rv.x; v.y += rv.y; v.z += rv.z; v.w += rv.w;
        }
        *(float4*)&out[(size_t)grow * 96 + j4 * 4] = v;
    }
}

// ---------------- mma fused edge message + aggregation ----------------------
// t = silu(A[send]+B[rec]+d*wl+b1); m = silu(t@W2+b2); aggr[rec] += m
__global__ void __launch_bounds__(512, 1)
mma_edge(const float* __restrict__ WT2, const float* __restrict__ WT2lo,
         const float* __restrict__ wl, const float* __restrict__ b1,
         const float* __restrict__ b2)
{
    extern __shared__ float sm[];
    uint32_t* As  = (uint32_t*)(sm + AHI);
    uint32_t* Bs  = (uint32_t*)(sm + BHI);
    uint32_t* Asl = (uint32_t*)(sm + ALO);
    uint32_t* Bsl = (uint32_t*)(sm + BLO);
    float*    Cs  = sm;
    float* b1s = sm + XTR;
    float* b2s = b1s + 96;
    float* wls = b2s + 96;
    float* de  = wls + 96;
    int*   se  = (int*)(de + 128);
    int*   re  = se + 128;

    const int tid = threadIdx.x;
    const int w   = tid >> 5, lane = tid & 31;
    const int wm  = w & 3, wn = w >> 2;
    const int tr  = lane >> 2, tc = lane & 3;
    const int base = blockIdx.x * 128;

    if (tid < 96) { b1s[tid] = b1[tid]; b2s[tid] = b2[tid]; wls[tid] = wl[tid]; }
    else if (tid >= 128 && tid < 256) {
        int j = tid - 128; int e = base + j;
        se[j] = g_send[e]; re[j] = g_rec[e]; de[j] = g_dist[e];
    }
    #pragma unroll
    for (int it = 0; it < 5; it++) {
        int idx = it * 512 + tid;
        if (idx < 96 * 24) {
            int n = idx / 24, k4 = idx - n * 24;
            float4 vh = *(const float4*)&WT2  [(size_t)n * 96 + k4 * 4];
            float4 vl = *(const float4*)&WT2lo[(size_t)n * 96 + k4 * 4];
            uint32_t *d = Bs + n * RS + k4, *dl = Bsl + n * RS + k4;
            d[0]  = __float_as_uint(vh.x); dl[0]  = __float_as_uint(vl.x);
            d[24] = __float_as_uint(vh.y); dl[24] = __float_as_uint(vl.y);
            d[48] = __float_as_uint(vh.z); dl[48] = __float_as_uint(vl.z);
            d[72] = __float_as_uint(vh.w); dl[72] = __float_as_uint(vl.w);
        }
    }
    __syncthreads();

    #pragma unroll
    for (int it = 0; it < 6; it++) {           // 128*24 / 512
        int idx = it * 512 + tid;
        int e = idx / 24, k4 = idx - e * 24;
        int kf = k4 * 4;
        int s = se[e], r = re[e];
        float dd = de[e];
        float4 a  = *(const float4*)&g_A[(size_t)s * 96 + kf];
        float4 b  = *(const float4*)&g_B[(size_t)r * 96 + kf];
        float4 w4 = *(const float4*)&wls[kf];
        float4 c4 = *(const float4*)&b1s[kf];
        uint32_t *d = As + e * RS + k4, *dl = Asl + e * RS + k4;
        tf32split(silu_f(a.x + b.x + dd * w4.x + c4.x), d[0],  dl[0]);
        tf32split(silu_f(a.y + b.y + dd * w4.y + c4.y), d[24], dl[24]);
        tf32split(silu_f(a.z + b.z + dd * w4.z + c4.z), d[48], dl[48]);
        tf32split(silu_f(a.w + b.w + dd * w4.w + c4.w), d[72], dl[72]);
    }
    __syncthreads();

    float acc[2][3][4];
    #pragma unroll
    for (int mf = 0; mf < 2; mf++)
        #pragma unroll
        for (int nf = 0; nf < 3; nf++)
            #pragma unroll
            for (int c = 0; c < 4; c++) acc[mf][nf][c] = 0.0f;

    const uint32_t* ap = As + (wm * 32 + tr) * RS + tc * 24;
    const uint32_t* bp = Bs + (wn * 24 + tr) * RS + tc * 24;
    mma3_loop(ap, bp, acc);
    __syncthreads();

    #pragma unroll
    for (int mf = 0; mf < 2; mf++) {
        int row = wm * 32 + mf * 16 + tr;
        #pragma unroll
        for (int nf = 0; nf < 3; nf++) {
            int col = wn * 24 + nf * 8 + 2 * tc;
            Cs[row * RS + col]       = acc[mf][nf][0];
            Cs[row * RS + col + 1]   = acc[mf][nf][1];
            Cs[(row+8) * RS + col]   = acc[mf][nf][2];
            Cs[(row+8) * RS + col+1] = acc[mf][nf][3];
        }
    }
    __syncthreads();

    #pragma unroll
    for (int it = 0; it < 6; it++) {
        int idx = it * 512 + tid;
        int row = idx / 24, j4 = idx - row * 24;
        float4 v = *(const float4*)&Cs[row * RS + j4 * 4];
        float4 b = *(const float4*)&b2s[j4 * 4];
        float4 m;
        m.x = silu_f(v.x + b.x); m.y = silu_f(v.y + b.y);
        m.z = silu_f(v.z + b.z); m.w = silu_f(v.w + b.w);
        red_add_v4(&g_aggr[(size_t)re[row] * 96 + j4 * 4], m);
    }
}

// ---------------- scalar node MLP (embed layer 1 only, K=11+24) -------------
__global__ void __launch_bounds__(384, 2)
node_mlp(const float* __restrict__ in1, int K1, const float* __restrict__ W1,
         const float* __restrict__ in2, int K2, const float* __restrict__ W2,
         const float* __restrict__ bias, float* __restrict__ out,
         int nrows, int do_silu)
{
    extern __shared__ float smf[];
    const int K1p = (K1 + 3) & ~3;
    const int K2p = (K2 + 3) & ~3;
    float* Ws1 = smf;
    float* Ws2 = smf + K1p * 96;
    float* sT  = Ws2 + K2p * 96;

    const int tid  = threadIdx.y * 24 + threadIdx.x;
    const int base = blockIdx.x * 64;
    const int f0   = threadIdx.x * 4;
    const int r0   = threadIdx.y * 4;

    for (int idx = tid; idx < K1p * 96; idx += 384) {
        int k = idx / 96;
        Ws1[idx] = (k < K1) ? W1[idx] : 0.0f;
    }
    if (in2) {
        for (int idx = tid; idx < K2p * 96; idx += 384) {
            int k = idx / 96;
            Ws2[idx] = (k < K2) ? W2[idx] : 0.0f;
        }
    }

    float acc[4][4];
    #pragma unroll
    for (int i = 0; i < 4; i++)
        #pragma unroll
        for (int c = 0; c < 4; c++) acc[i][c] = 0.0f;

    for (int idx = tid; idx < 64 * K1p; idx += 384) {
        int k = idx / 64, e = idx - (k * 64);
        int row = base + e;
        sT[k*64 + e] = (k < K1 && row < nrows) ? in1[(size_t)row * K1 + k] : 0.0f;
    }
    __syncthreads();
    for (int k = 0; k < K1p; k++) {
        float4 w = *(const float4*)&Ws1[k*96 + f0];
        #pragma unroll
        for (int i = 0; i < 4; i++) {
            float tv = sT[k*64 + r0 + i];
            acc[i][0] += tv * w.x; acc[i][1] += tv * w.y;
            acc[i][2] += tv * w.z; acc[i][3] += tv * w.w;
        }
    }
    if (in2) {
        __syncthreads();
        for (int idx = tid; idx < 64 * K2p; idx += 384) {
            int k = idx / 64, e = idx - (k * 64);
            int row = base + e;
            sT[k*64 + e] = (k < K2 && row < nrows) ? in2[(size_t)row * K2 + k] : 0.0f;
        }
        __syncthreads();
        for (int k = 0; k < K2p; k++) {
            float4 w = *(const float4*)&Ws2[k*96 + f0];
            #pragma unroll
            for (int i = 0; i < 4; i++) {
                float tv = sT[k*64 + r0 + i];
                acc[i][0] += tv * w.x; acc[i][1] += tv * w.y;
                acc[i][2] += tv * w.z; acc[i][3] += tv * w.w;
            }
        }
    }
    #pragma unroll
    for (int i = 0; i < 4; i++) {
        int row = base + r0 + i;
        if (row >= nrows) continue;
        float4 v;
        v.x = acc[i][0] + bias[f0+0];
        v.y = acc[i][1] + bias[f0+1];
        v.z = acc[i][2] + bias[f0+2];
        v.w = acc[i][3] + bias[f0+3];
        if (do_silu) {
            v.x = silu_f(v.x); v.y = silu_f(v.y);
            v.z = silu_f(v.z); v.w = silu_f(v.w);
        }
        *(float4*)&out[(size_t)row*96 + f0] = v;
    }
}

// ---------------- zero / pooling / readout ----------------------------------
__global__ void zero_aggr_kernel() {
    int i = blockIdx.x * 1024 + threadIdx.x;
    if (i < N_NODES * HDIM) g_aggr[i] = 0.0f;
}
__global__ void zero_pooled_kernel() {
    int i = blockIdx.x * 256 + threadIdx.x;
    if (i < N_GRAPHS * HDIM) g_pooled[i] = 0.0f;
}
__global__ void pool_kernel(const float* __restrict__ h2, const int* __restrict__ braw) {
    __shared__ int s_is64;
    if (threadIdx.x == 0) {
        s_is64 = ((braw[N_NODES-1] | braw[N_NODES-3] |
                   braw[N_NODES-5] | braw[N_NODES-7]) == 0) ? 1 : 0;
    }
    __syncthreads();
    int idx = blockIdx.x * blockDim.x + threadIdx.x;
    if (idx >= N_NODES * 24) return;
    int n = idx / 24, j = idx - n * 24;
    int g = s_is64 ? (int)((const long long*)braw)[n] : braw[n];
    float4 v = *(const float4*)&h2[(size_t)n*96 + j*4];
    red_add_v4(&g_pooled[g*96 + j*4], v);
}
__global__ void readout_kernel(const float* __restrict__ w1, const float* __restrict__ b1,
                               const float* __restrict__ w2, const float* __restrict__ b2,
                               float* __restrict__ out)
{
    __shared__ float p_s[96];
    __shared__ float t_s[96];
    int g = blockIdx.x, f = threadIdx.x;
    p_s[f] = g_pooled[g*96 + f];
    __syncthreads();
    float a = b1[f];
    #pragma unroll 8
    for (int k = 0; k < 96; k++) a += p_s[k] * w1[k*96 + f];
    t_s[f] = silu_f(a) * w2[f];
    __syncthreads();
    if (f < 32) {
        float sum = t_s[f] + t_s[f+32] + t_s[f+64];
        #pragma unroll
        for (int o = 16; o > 0; o >>= 1) sum += __shfl_down_sync(0xffffffffu, sum, o);
        if (f == 0) out[g] = sum + b2[0];
    }
}

// ---------------- host launcher ----------------------------------------------
extern "C" void kernel_launch(void* const* d_in, const int* in_sizes, int n_in,
                              void* d_out, int out_size)
{
    const float* x    = (const float*)d_in[0];
    const float* pos  = (const float*)d_in[1];
    const float* pe   = (const float*)d_in[2];
    const int*   eraw = (const int*)d_in[3];
    const int*   braw = (const int*)d_in[4];
    const float* ew1  = (const float*)d_in[5];
    const float* eb1  = (const float*)d_in[6];
    const float* ew2  = (const float*)d_in[7];
    const float* eb2  = (const float*)d_in[8];
    const float* mw1  = (const float*)d_in[9];
    const float* mb1  = (const float*)d_in[10];
    const float* mw2  = (const float*)d_in[11];
    const float* mb2  = (const float*)d_in[12];
    const float* uw1  = (const float*)d_in[13];
    const float* ub1  = (const float*)d_in[14];
    const float* uw2  = (const float*)d_in[15];
    const float* ub2  = (const float*)d_in[16];
    const float* pw1  = (const float*)d_in[17];
    const float* pb1  = (const float*)d_in[18];
    const float* pw2  = (const float*)d_in[19];
    const float* pb2  = (const float*)d_in[20];
    const float* rw1  = (const float*)d_in[21];
    const float* rb1  = (const float*)d_in[22];
    const float* rw2  = (const float*)d_in[23];
    const float* rb2  = (const float*)d_in[24];
    float* out = (float*)d_out;

    float *h_, *A_, *B_, *aggr_, *u_, *WT_, *WTlo_;
    cudaGetSymbolAddress((void**)&h_,    g_h);
    cudaGetSymbolAddress((void**)&A_,    g_A);
    cudaGetSymbolAddress((void**)&B_,    g_B);
    cudaGetSymbolAddress((void**)&aggr_, g_aggr);
    cudaGetSymbolAddress((void**)&u_,    g_u);
    cudaGetSymbolAddress((void**)&WT_,   g_WT);
    cudaGetSymbolAddress((void**)&WTlo_, g_WTlo);

    cudaFuncSetAttribute((const void*)node_mlp,
                         cudaFuncAttributeMaxDynamicSharedMemorySize, 32768);
    cudaFuncSetAttribute((const void*)mma_node,
                         cudaFuncAttributeMaxDynamicSharedMemorySize, 180224);
    cudaFuncSetAttribute((const void*)mma_edge,
                         cudaFuncAttributeMaxDynamicSharedMemorySize, 184320);

    // smem: hi/lo A (2*12800) + hi/lo B (2*9600) = 44800 floats = 179200 B
    const size_t smN = 179200;
    const size_t smE = 179200 + (96*3 + 128*3) * 4;   // 181888
    const int    nblk = (N_NODES + 127) / 128;        // 391

    edge_prep<<<(N_EDGES + 255) / 256, 256>>>(eraw, pos);
    transpose_all<<<243, 1024>>>(mw1, mw2, uw1, uw2, ew2, pw1, pw2);
    split_weights<<<243, 1024>>>();

    // embed layer 1 (scalar, K=11+24): u = silu([x,pe]@W1 + b1)
    {
        int K1p = 12, K2p = 24;
        size_t smem = (size_t)(K1p + K2p) * 96 * 4 + (size_t)64 * 24 * 4;
        dim3 tb(24, 16);
        node_mlp<<<(N_NODES + 63) / 64, tb, smem>>>(
            x, NUM_IN, ew1, pe, PE_DIM, ew1 + NUM_IN * 96, eb1, u_, N_NODES, 1);
    }
    // embed layer 2: h = u @ W2 + b2
    mma_node<<<nblk, 512, smN>>>(u_, nullptr, WT_ + 221184, WTlo_ + 221184, 96,
                                 eb2, nullptr, h_, N_NODES, 0);

    for (int l = 0; l < N_LAYERS; l++) {
        size_t off = (size_t)l * 55296;
        const float* mb1l = mb1 + l * 96;
        const float* mb2l = mb2 + l * 96;
        const float* ub1l = ub1 + l * 96;
        const float* ub2l = ub2 + l * 96;
        const float* wll  = mw1 + (size_t)l * 193 * 96 + 192 * 96;  // dist row

        mma_node<<<nblk, 512, smN>>>(h_, nullptr, WT_ + off, WTlo_ + off, 96,
                                     nullptr, nullptr, A_, N_NODES, 0);
        mma_node<<<nblk, 512, smN>>>(h_, nullptr, WT_ + off + 9216, WTlo_ + off + 9216, 96,
                                     nullptr, nullptr, B_, N_NODES, 0);

        zero_aggr_kernel<<<(N_NODES * HDIM + 1023) / 1024, 1024>>>();
        mma_edge<<<N_EDGES / 128, 512, smE>>>(WT_ + off + 18432, WTlo_ + off + 18432,
                                              wll, mb1l, mb2l);

        mma_node<<<nblk, 512, smN>>>(h_, aggr_, WT_ + off + 27648, WTlo_ + off + 27648, 192,
                                     ub1l, nullptr, u_, N_NODES, 1);
        mma_node<<<nblk, 512, smN>>>(u_, nullptr, WT_ + off + 46080, WTlo_ + off + 46080, 96,
                                     ub2l, h_, h_, N_NODES, 0);
    }

    // pre-MLP -> h2 (stored in g_A)
    mma_node<<<nblk, 512, smN>>>(h_, nullptr, WT_ + 230400, WTlo_ + 230400, 96,
                                 pb1, nullptr, u_, N_NODES, 1);
    mma_node<<<nblk, 512, smN>>>(u_, nullptr, WT_ + 239616, WTlo_ + 239616, 96,
                                 pb2, nullptr, A_, N_NODES, 0);

    zero_pooled_kernel<<<(N_GRAPHS * HDIM + 255) / 256, 256>>>();
    pool_kernel<<<(N_NODES * 24 + 255) / 256, 256>>>(A_, braw);
    readout_kernel<<<N_GRAPHS, 96>>>(rw1, rb1, rw2, rb2, out);
}